// round 5
// baseline (speedup 1.0000x reference)
#include <cuda_runtime.h>

#define NB 16
#define SECL 16
#define WORDL 256
#define SLEN 4096
#define DIM 1024
#define FSZ 2
#define GATH (FSZ*WORDL)   // 512
#define NPART 64           // k5 context partials (one per 8-row chunk)

// ---------------- scratch (device globals; no allocation) ----------------
__device__ float g_decfeat[NB*DIM];
__device__ float g_scores[NB*GATH];
__device__ float g_attn[NB*GATH];
__device__ float g_ctxpart[NPART*NB*DIM];   // 4 MB

// accurate tanh: 1 - 2/(e^{2x}+1), ex2/rcp MUFU (~1e-7 abs error)
__device__ __forceinline__ float fast_tanh(float x) {
    float e;
    asm("ex2.approx.f32 %0, %1;" : "=f"(e) : "f"(x * 2.8853900817779268f)); // 2*log2(e)
    float r;
    asm("rcp.approx.f32 %0, %1;" : "=f"(r) : "f"(e + 1.0f));
    return 1.0f - 2.0f * r;
}

// top-2 of focus[b] (jax first-occurrence tie rule); run by ONE thread
__device__ __forceinline__ void top2_focus(const float* __restrict__ focus, int b,
                                           int& i0, int& i1, float& v0, float& v1) {
    const float* f = focus + b*SECL;
    v0 = -__int_as_float(0x7f800000); i0 = 0;
#pragma unroll
    for (int j = 0; j < SECL; j++) { float x = __ldg(&f[j]); if (x > v0) { v0 = x; i0 = j; } }
    v1 = -__int_as_float(0x7f800000); i1 = 0;
#pragma unroll
    for (int j = 0; j < SECL; j++) {
        if (j == i0) continue;
        float x = __ldg(&f[j]); if (x > v1) { v1 = x; i1 = j; }
    }
}

// ---------------- K1: dec_feature = dec_hidden @ W_dec^T + b_dec ----------------
// 128 blocks * 256 threads; each warp owns 1 output dim, loops all 16 batches. (R3-proven)
__global__ __launch_bounds__(256) void k1_decproj(const float* __restrict__ h,
                                                  const float* __restrict__ W,
                                                  const float* __restrict__ bvec) {
    int warp = threadIdx.x >> 5;
    int lane = threadIdx.x & 31;
    int d = blockIdx.x*8 + warp;
    const float4* Wd = (const float4*)(W + (size_t)d*DIM);
    const float4* h4 = (const float4*)h;
    float acc[NB];
#pragma unroll
    for (int b = 0; b < NB; b++) acc[b] = 0.f;
#pragma unroll
    for (int i = 0; i < 8; i++) {
        int kk = lane + i*32;
        float4 w = __ldg(&Wd[kk]);
#pragma unroll
        for (int b = 0; b < NB; b++) {
            float4 hb = __ldg(&h4[b*256 + kk]);
            acc[b] = fmaf(w.x, hb.x, fmaf(w.y, hb.y, fmaf(w.z, hb.z, fmaf(w.w, hb.w, acc[b]))));
        }
    }
#pragma unroll
    for (int b = 0; b < NB; b++) {
#pragma unroll
        for (int o = 16; o > 0; o >>= 1)
            acc[b] += __shfl_xor_sync(0xffffffffu, acc[b], o);
    }
    if (lane == 0) {
        float bd = bvec[d];
#pragma unroll
        for (int b = 0; b < NB; b++)
            g_decfeat[b*DIM + d] = acc[b] + bd;
    }
}

// ---------------- K3: scores on gathered sections only ----------------
// one warp per gathered position; 1024 blocks * 256 threads (8 warps, same b)
__global__ __launch_bounds__(256) void k3_scores(const float* __restrict__ enc_feature,
                                                 const float* __restrict__ coverage,
                                                 const float* __restrict__ vvec,
                                                 const float* __restrict__ w_cov,
                                                 const float* __restrict__ focus) {
    __shared__ int sh_sec[2];
    int warp = threadIdx.x >> 5;
    int lane = threadIdx.x & 31;
    int gw = blockIdx.x*8 + warp;
    int b = gw >> 9;
    int r = gw & 511;
    if (threadIdx.x == 0) {
        int i0, i1; float v0, v1;
        top2_focus(focus, b, i0, i1, v0, v1);
        sh_sec[0] = i0; sh_sec[1] = i1;
    }
    __syncthreads();
    int sec = sh_sec[r >> 8];
    int s = sec*WORDL + (r & 255);
    float cov = coverage[b*SLEN + s];
    const float4* ef  = (const float4*)(enc_feature + ((size_t)(b*SLEN + s))*DIM);
    const float4* df  = (const float4*)(g_decfeat + b*DIM);
    const float4* v4  = (const float4*)vvec;
    const float4* wc4 = (const float4*)w_cov;
    float acc = 0.f;
#pragma unroll
    for (int i = 0; i < 8; i++) {
        int kk = lane + i*32;
        float4 e  = __ldg(&ef[kk]);
        float4 dd = df[kk];
        float4 vv = __ldg(&v4[kk]);
        float4 wc = __ldg(&wc4[kk]);
        acc += vv.x * fast_tanh(fmaf(cov, wc.x, e.x + dd.x));
        acc += vv.y * fast_tanh(fmaf(cov, wc.y, e.y + dd.y));
        acc += vv.z * fast_tanh(fmaf(cov, wc.z, e.z + dd.z));
        acc += vv.w * fast_tanh(fmaf(cov, wc.w, e.w + dd.w));
    }
#pragma unroll
    for (int o = 16; o > 0; o >>= 1) acc += __shfl_xor_sync(0xffffffffu, acc, o);
    if (lane == 0) g_scores[b*GATH + r] = acc;
}

// ---------------- block reduce helper (512 threads) ----------------
__device__ __forceinline__ float blkred(float v, float* red, bool is_max) {
#pragma unroll
    for (int o = 16; o > 0; o >>= 1) {
        float t = __shfl_xor_sync(0xffffffffu, v, o);
        v = is_max ? fmaxf(v, t) : (v + t);
    }
    __syncthreads();
    if ((threadIdx.x & 31) == 0) red[threadIdx.x >> 5] = v;
    __syncthreads();
    if (threadIdx.x < 32) {
        float x = (threadIdx.x < 16) ? red[threadIdx.x]
                                     : (is_max ? -__int_as_float(0x7f800000) : 0.f);
#pragma unroll
        for (int o = 8; o > 0; o >>= 1) {
            float t = __shfl_xor_sync(0xffffffffu, x, o);
            x = is_max ? fmaxf(x, t) : (x + t);
        }
        if (threadIdx.x == 0) red[0] = x;
    }
    __syncthreads();
    return red[0];
}

// ---------------- K4: softmax (scale-invariant form) -> g_attn ----------------
__global__ __launch_bounds__(512) void k4_softmax(const float* __restrict__ enc_mask,
                                                  const float* __restrict__ focus) {
    __shared__ float red[16];
    __shared__ int   sh_sec[2];
    __shared__ float sh_tv[2];
    int b = blockIdx.x;
    int j = threadIdx.x;
    if (j == 0) {
        int i0, i1; float v0, v1;
        top2_focus(focus, b, i0, i1, v0, v1);
        sh_sec[0] = i0; sh_sec[1] = i1; sh_tv[0] = v0; sh_tv[1] = v1;
    }
    __syncthreads();
    int f = j >> 8;
    int s = sh_sec[f]*WORDL + (j & 255);
    float tv = sh_tv[f];
    float sc = g_scores[b*GATH + j];
    float m  = enc_mask[b*SLEN + s];

    float mx   = blkred(sc, red, true);
    float a0   = __expf(sc - mx) * m;
    float sum2 = blkred(a0, red, false);
    float a1   = tv * (a0 / sum2);
    float sum3 = blkred(a1, red, false);
    g_attn[b*GATH + j] = a1 / sum3;
}

// ---------------- K5: context partials — 8 rows/thread, explicit front-batched loads ----------------
// grid (16 b, 64 chunks of 8 rows), 256 threads; thread owns one float4 of DIM.
__global__ __launch_bounds__(256) void k5_ctx(const float* __restrict__ enc_output,
                                              const float* __restrict__ focus) {
    __shared__ float sh_a[8];
    __shared__ int sh_sec;
    int b = blockIdx.x;
    int c = blockIdx.y;            // 0..63
    int f = c >> 5;
    int w0 = (c & 31) * 8;
    if (threadIdx.x == 0) {
        int i0, i1; float v0, v1;
        top2_focus(focus, b, i0, i1, v0, v1);
        sh_sec = f ? i1 : i0;
    }
    if (threadIdx.x >= 32 && threadIdx.x < 40)
        sh_a[threadIdx.x - 32] = g_attn[b*GATH + f*WORDL + w0 + (threadIdx.x - 32)];
    __syncthreads();
    const float4* base = (const float4*)(enc_output
        + ((size_t)(b*SLEN + sh_sec*WORDL + w0))*DIM) + threadIdx.x;
    // front-batch all 8 row loads (8 independent LDG.128 in flight)
    float4 r0 = __ldg(base + 0*(DIM/4));
    float4 r1 = __ldg(base + 1*(DIM/4));
    float4 r2 = __ldg(base + 2*(DIM/4));
    float4 r3 = __ldg(base + 3*(DIM/4));
    float4 r4 = __ldg(base + 4*(DIM/4));
    float4 r5 = __ldg(base + 5*(DIM/4));
    float4 r6 = __ldg(base + 6*(DIM/4));
    float4 r7 = __ldg(base + 7*(DIM/4));
    float c0 = sh_a[0], c1 = sh_a[1], c2 = sh_a[2], c3 = sh_a[3];
    float c4 = sh_a[4], c5 = sh_a[5], c6 = sh_a[6], c7 = sh_a[7];
    float4 s;
    s.x = (fmaf(c0,r0.x, c1*r1.x) + fmaf(c2,r2.x, c3*r3.x))
        + (fmaf(c4,r4.x, c5*r5.x) + fmaf(c6,r6.x, c7*r7.x));
    s.y = (fmaf(c0,r0.y, c1*r1.y) + fmaf(c2,r2.y, c3*r3.y))
        + (fmaf(c4,r4.y, c5*r5.y) + fmaf(c6,r6.y, c7*r7.y));
    s.z = (fmaf(c0,r0.z, c1*r1.z) + fmaf(c2,r2.z, c3*r3.z))
        + (fmaf(c4,r4.z, c5*r5.z) + fmaf(c6,r6.z, c7*r7.z));
    s.w = (fmaf(c0,r0.w, c1*r1.w) + fmaf(c2,r2.w, c3*r3.w))
        + (fmaf(c4,r4.w, c5*r5.w) + fmaf(c6,r6.w, c7*r7.w));
    *((float4*)(g_ctxpart + ((size_t)(c*NB + b))*DIM) + threadIdx.x) = s;
}

// ---------------- K6: fused epilogue — context combine + wide scatter ----------------
// blocks [0,16): sum NPART context partials. blocks [16,80): attn_dist + coverage_out.
__global__ __launch_bounds__(256) void k6_epilogue(const float* __restrict__ coverage,
                                                   const float* __restrict__ focus,
                                                   float* __restrict__ out) {
    if (blockIdx.x < 16) {
        int b = blockIdx.x;
        int t = threadIdx.x;                        // float4 index within dim, 256 per batch
        const float4* cp = (const float4*)g_ctxpart + b*(DIM/4) + t;
        float4 s0 = make_float4(0,0,0,0), s1 = s0, s2 = s0, s3 = s0;
#pragma unroll
        for (int p = 0; p < NPART; p += 4) {
            float4 t0 = cp[(size_t)(p+0)*(NB*DIM/4)];
            float4 t1 = cp[(size_t)(p+1)*(NB*DIM/4)];
            float4 t2 = cp[(size_t)(p+2)*(NB*DIM/4)];
            float4 t3 = cp[(size_t)(p+3)*(NB*DIM/4)];
            s0.x += t0.x; s0.y += t0.y; s0.z += t0.z; s0.w += t0.w;
            s1.x += t1.x; s1.y += t1.y; s1.z += t1.z; s1.w += t1.w;
            s2.x += t2.x; s2.y += t2.y; s2.z += t2.z; s2.w += t2.w;
            s3.x += t3.x; s3.y += t3.y; s3.z += t3.z; s3.w += t3.w;
        }
        float4 s = make_float4((s0.x+s1.x)+(s2.x+s3.x), (s0.y+s1.y)+(s2.y+s3.y),
                               (s0.z+s1.z)+(s2.z+s3.z), (s0.w+s1.w)+(s2.w+s3.w));
        ((float4*)out)[b*(DIM/4) + t] = s;
    } else {
        __shared__ int sh_i0, sh_i1;
        int gb = blockIdx.x - 16;                   // 64 blocks; 4 per batch
        int b  = gb >> 2;
        if (threadIdx.x == 0) {
            int i0, i1; float v0, v1;
            top2_focus(focus, b, i0, i1, v0, v1);
            sh_i0 = i0; sh_i1 = i1;
        }
        __syncthreads();
        int p4 = (gb & 3)*256 + threadIdx.x;        // float4 index within batch, 0..1023
        int pos = p4 << 2;
        int si = pos >> 8;
        int w  = pos & 255;
        float4 av = make_float4(0.f, 0.f, 0.f, 0.f);
        if (si == sh_i0)      av = *(const float4*)(g_attn + b*GATH + w);
        else if (si == sh_i1) av = *(const float4*)(g_attn + b*GATH + WORDL + w);
        float4 cv = __ldg((const float4*)(coverage + b*SLEN) + p4);
        float4* oa = (float4*)(out + NB*DIM + b*SLEN);
        float4* oc = (float4*)(out + NB*DIM + NB*SLEN + b*SLEN);
        oa[p4] = av;
        oc[p4] = make_float4(cv.x + av.x, cv.y + av.y, cv.z + av.z, cv.w + av.w);
    }
}

extern "C" void kernel_launch(void* const* d_in, const int* in_sizes, int n_in,
                              void* d_out, int out_size) {
    const float* dec_hidden  = (const float*)d_in[0];
    const float* enc_output  = (const float*)d_in[1];
    const float* enc_feature = (const float*)d_in[2];
    const float* enc_mask    = (const float*)d_in[3];
    // d_in[4] = sec_attn (unused by reference)
    const float* coverage    = (const float*)d_in[5];
    const float* focus       = (const float*)d_in[6];
    const float* W_dec       = (const float*)d_in[7];
    const float* b_dec       = (const float*)d_in[8];
    const float* vvec        = (const float*)d_in[9];
    const float* w_cov       = (const float*)d_in[10];
    float* out = (float*)d_out;

    k1_decproj<<<128, 256>>>(dec_hidden, W_dec, b_dec);
    k3_scores<<<1024, 256>>>(enc_feature, coverage, vvec, w_cov, focus);
    k4_softmax<<<16, 512>>>(enc_mask, focus);
    k5_ctx<<<dim3(16, 64), 256>>>(enc_output, focus);
    k6_epilogue<<<80, 256>>>(coverage, focus, out);
}

// round 6
// speedup vs baseline: 1.0599x; 1.0599x over previous
#include <cuda_runtime.h>

#define NB 16
#define SECL 16
#define WORDL 256
#define SLEN 4096
#define DIM 1024
#define FSZ 2
#define GATH (FSZ*WORDL)   // 512
#define NPART 16           // k5 context partials (one per 32-row chunk)

// ---------------- scratch (device globals; no allocation) ----------------
__device__ float g_decfeat[NB*DIM];
__device__ float g_scores[NB*GATH];
__device__ float g_attn[NB*GATH];
__device__ float g_ctxpart[NPART*NB*DIM];   // 1 MB

// accurate tanh: 1 - 2/(e^{2x}+1), ex2/rcp MUFU (~1e-7 abs error)
__device__ __forceinline__ float fast_tanh(float x) {
    float e;
    asm("ex2.approx.f32 %0, %1;" : "=f"(e) : "f"(x * 2.8853900817779268f)); // 2*log2(e)
    float r;
    asm("rcp.approx.f32 %0, %1;" : "=f"(r) : "f"(e + 1.0f));
    return 1.0f - 2.0f * r;
}

// top-2 of focus[b] (jax first-occurrence tie rule); run by ONE thread
__device__ __forceinline__ void top2_focus(const float* __restrict__ focus, int b,
                                           int& i0, int& i1, float& v0, float& v1) {
    const float* f = focus + b*SECL;
    v0 = -__int_as_float(0x7f800000); i0 = 0;
#pragma unroll
    for (int j = 0; j < SECL; j++) { float x = __ldg(&f[j]); if (x > v0) { v0 = x; i0 = j; } }
    v1 = -__int_as_float(0x7f800000); i1 = 0;
#pragma unroll
    for (int j = 0; j < SECL; j++) {
        if (j == i0) continue;
        float x = __ldg(&f[j]); if (x > v1) { v1 = x; i1 = j; }
    }
}

// ---------------- K1: dec_feature = dec_hidden @ W_dec^T + b_dec ----------------
// 128 blocks * 256 threads; each warp owns 1 output dim, loops all 16 batches.
__global__ __launch_bounds__(256) void k1_decproj(const float* __restrict__ h,
                                                  const float* __restrict__ W,
                                                  const float* __restrict__ bvec) {
    int warp = threadIdx.x >> 5;
    int lane = threadIdx.x & 31;
    int d = blockIdx.x*8 + warp;
    const float4* Wd = (const float4*)(W + (size_t)d*DIM);
    const float4* h4 = (const float4*)h;
    float acc[NB];
#pragma unroll
    for (int b = 0; b < NB; b++) acc[b] = 0.f;
#pragma unroll
    for (int i = 0; i < 8; i++) {
        int kk = lane + i*32;
        float4 w = __ldg(&Wd[kk]);
#pragma unroll
        for (int b = 0; b < NB; b++) {
            float4 hb = __ldg(&h4[b*256 + kk]);
            acc[b] = fmaf(w.x, hb.x, fmaf(w.y, hb.y, fmaf(w.z, hb.z, fmaf(w.w, hb.w, acc[b]))));
        }
    }
#pragma unroll
    for (int b = 0; b < NB; b++) {
#pragma unroll
        for (int o = 16; o > 0; o >>= 1)
            acc[b] += __shfl_xor_sync(0xffffffffu, acc[b], o);
    }
    if (lane == 0) {
        float bd = bvec[d];
#pragma unroll
        for (int b = 0; b < NB; b++)
            g_decfeat[b*DIM + d] = acc[b] + bd;
    }
}

// ---------------- K3: scores on gathered sections only ----------------
// one warp per gathered position; 1024 blocks * 256 threads (8 warps, same b)
__global__ __launch_bounds__(256) void k3_scores(const float* __restrict__ enc_feature,
                                                 const float* __restrict__ coverage,
                                                 const float* __restrict__ vvec,
                                                 const float* __restrict__ w_cov,
                                                 const float* __restrict__ focus) {
    __shared__ int sh_sec[2];
    int warp = threadIdx.x >> 5;
    int lane = threadIdx.x & 31;
    int gw = blockIdx.x*8 + warp;
    int b = gw >> 9;
    int r = gw & 511;
    if (threadIdx.x == 0) {
        int i0, i1; float v0, v1;
        top2_focus(focus, b, i0, i1, v0, v1);
        sh_sec[0] = i0; sh_sec[1] = i1;
    }
    __syncthreads();
    int sec = sh_sec[r >> 8];
    int s = sec*WORDL + (r & 255);
    float cov = coverage[b*SLEN + s];
    const float4* ef  = (const float4*)(enc_feature + ((size_t)(b*SLEN + s))*DIM);
    const float4* df  = (const float4*)(g_decfeat + b*DIM);
    const float4* v4  = (const float4*)vvec;
    const float4* wc4 = (const float4*)w_cov;
    float acc = 0.f;
#pragma unroll
    for (int i = 0; i < 8; i++) {
        int kk = lane + i*32;
        float4 e  = __ldg(&ef[kk]);
        float4 dd = df[kk];
        float4 vv = __ldg(&v4[kk]);
        float4 wc = __ldg(&wc4[kk]);
        acc += vv.x * fast_tanh(fmaf(cov, wc.x, e.x + dd.x));
        acc += vv.y * fast_tanh(fmaf(cov, wc.y, e.y + dd.y));
        acc += vv.z * fast_tanh(fmaf(cov, wc.z, e.z + dd.z));
        acc += vv.w * fast_tanh(fmaf(cov, wc.w, e.w + dd.w));
    }
#pragma unroll
    for (int o = 16; o > 0; o >>= 1) acc += __shfl_xor_sync(0xffffffffu, acc, o);
    if (lane == 0) g_scores[b*GATH + r] = acc;
}

// ---------------- block reduce helper (512 threads) ----------------
__device__ __forceinline__ float blkred(float v, float* red, bool is_max) {
#pragma unroll
    for (int o = 16; o > 0; o >>= 1) {
        float t = __shfl_xor_sync(0xffffffffu, v, o);
        v = is_max ? fmaxf(v, t) : (v + t);
    }
    __syncthreads();
    if ((threadIdx.x & 31) == 0) red[threadIdx.x >> 5] = v;
    __syncthreads();
    if (threadIdx.x < 32) {
        float x = (threadIdx.x < 16) ? red[threadIdx.x]
                                     : (is_max ? -__int_as_float(0x7f800000) : 0.f);
#pragma unroll
        for (int o = 8; o > 0; o >>= 1) {
            float t = __shfl_xor_sync(0xffffffffu, x, o);
            x = is_max ? fmaxf(x, t) : (x + t);
        }
        if (threadIdx.x == 0) red[0] = x;
    }
    __syncthreads();
    return red[0];
}

// ---------------- K4: softmax (scale-invariant form) -> g_attn ----------------
__global__ __launch_bounds__(512) void k4_softmax(const float* __restrict__ enc_mask,
                                                  const float* __restrict__ focus) {
    __shared__ float red[16];
    __shared__ int   sh_sec[2];
    __shared__ float sh_tv[2];
    int b = blockIdx.x;
    int j = threadIdx.x;
    if (j == 0) {
        int i0, i1; float v0, v1;
        top2_focus(focus, b, i0, i1, v0, v1);
        sh_sec[0] = i0; sh_sec[1] = i1; sh_tv[0] = v0; sh_tv[1] = v1;
    }
    __syncthreads();
    int f = j >> 8;
    int s = sh_sec[f]*WORDL + (j & 255);
    float tv = sh_tv[f];
    float sc = g_scores[b*GATH + j];
    float m  = enc_mask[b*SLEN + s];

    float mx   = blkred(sc, red, true);
    float a0   = __expf(sc - mx) * m;
    float sum2 = blkred(a0, red, false);
    float a1   = tv * (a0 / sum2);
    float sum3 = blkred(a1, red, false);
    g_attn[b*GATH + j] = a1 / sum3;
}

// ---------------- K5: context partials — 32 rows/block, 4 iters of 8 front-batched rows ----------------
// grid (16 b, 16 chunks), 256 threads; thread owns one float4 of DIM.
__global__ __launch_bounds__(256) void k5_ctx(const float* __restrict__ enc_output,
                                              const float* __restrict__ focus) {
    __shared__ float sh_a[32];
    __shared__ int sh_sec;
    int b = blockIdx.x;
    int c = blockIdx.y;            // 0..15
    int f = c >> 3;
    int w0 = (c & 7) * 32;
    if (threadIdx.x == 0) {
        int i0, i1; float v0, v1;
        top2_focus(focus, b, i0, i1, v0, v1);
        sh_sec = f ? i1 : i0;
    }
    if (threadIdx.x >= 32 && threadIdx.x < 64)
        sh_a[threadIdx.x - 32] = g_attn[b*GATH + f*WORDL + w0 + (threadIdx.x - 32)];
    __syncthreads();
    const float4* base = (const float4*)(enc_output
        + ((size_t)(b*SLEN + sh_sec*WORDL + w0))*DIM) + threadIdx.x;
    float4 acc = make_float4(0.f, 0.f, 0.f, 0.f);
#pragma unroll
    for (int it = 0; it < 4; it++) {
        const float4* p = base + (size_t)(it*8)*(DIM/4);
        // front-batch 8 independent LDG.128
        float4 r0 = __ldg(p + 0*(DIM/4));
        float4 r1 = __ldg(p + 1*(DIM/4));
        float4 r2 = __ldg(p + 2*(DIM/4));
        float4 r3 = __ldg(p + 3*(DIM/4));
        float4 r4 = __ldg(p + 4*(DIM/4));
        float4 r5 = __ldg(p + 5*(DIM/4));
        float4 r6 = __ldg(p + 6*(DIM/4));
        float4 r7 = __ldg(p + 7*(DIM/4));
        float c0 = sh_a[it*8+0], c1 = sh_a[it*8+1], c2 = sh_a[it*8+2], c3 = sh_a[it*8+3];
        float c4 = sh_a[it*8+4], c5 = sh_a[it*8+5], c6 = sh_a[it*8+6], c7 = sh_a[it*8+7];
        acc.x += (fmaf(c0,r0.x, c1*r1.x) + fmaf(c2,r2.x, c3*r3.x))
               + (fmaf(c4,r4.x, c5*r5.x) + fmaf(c6,r6.x, c7*r7.x));
        acc.y += (fmaf(c0,r0.y, c1*r1.y) + fmaf(c2,r2.y, c3*r3.y))
               + (fmaf(c4,r4.y, c5*r5.y) + fmaf(c6,r6.y, c7*r7.y));
        acc.z += (fmaf(c0,r0.z, c1*r1.z) + fmaf(c2,r2.z, c3*r3.z))
               + (fmaf(c4,r4.z, c5*r5.z) + fmaf(c6,r6.z, c7*r7.z));
        acc.w += (fmaf(c0,r0.w, c1*r1.w) + fmaf(c2,r2.w, c3*r3.w))
               + (fmaf(c4,r4.w, c5*r5.w) + fmaf(c6,r6.w, c7*r7.w));
    }
    *((float4*)(g_ctxpart + ((size_t)(c*NB + b))*DIM) + threadIdx.x) = acc;
}

// ---------------- K6: fused epilogue — context combine + wide scatter ----------------
// blocks [0,16): sum NPART context partials (global float4 index). blocks [16,80): scatter.
__global__ __launch_bounds__(256) void k6_epilogue(const float* __restrict__ coverage,
                                                   const float* __restrict__ focus,
                                                   float* __restrict__ out) {
    if (blockIdx.x < 16) {
        int i = blockIdx.x*256 + threadIdx.x;       // float4 index, 4096 total (all b*dim)
        const float4* cp = (const float4*)g_ctxpart + i;
        float4 s0 = make_float4(0,0,0,0), s1 = s0, s2 = s0, s3 = s0;
#pragma unroll
        for (int p = 0; p < NPART; p += 4) {
            float4 t0 = cp[(size_t)(p+0)*(NB*DIM/4)];
            float4 t1 = cp[(size_t)(p+1)*(NB*DIM/4)];
            float4 t2 = cp[(size_t)(p+2)*(NB*DIM/4)];
            float4 t3 = cp[(size_t)(p+3)*(NB*DIM/4)];
            s0.x += t0.x; s0.y += t0.y; s0.z += t0.z; s0.w += t0.w;
            s1.x += t1.x; s1.y += t1.y; s1.z += t1.z; s1.w += t1.w;
            s2.x += t2.x; s2.y += t2.y; s2.z += t2.z; s2.w += t2.w;
            s3.x += t3.x; s3.y += t3.y; s3.z += t3.z; s3.w += t3.w;
        }
        float4 s = make_float4((s0.x+s1.x)+(s2.x+s3.x), (s0.y+s1.y)+(s2.y+s3.y),
                               (s0.z+s1.z)+(s2.z+s3.z), (s0.w+s1.w)+(s2.w+s3.w));
        ((float4*)out)[i] = s;
    } else {
        __shared__ int sh_i0, sh_i1;
        int gb = blockIdx.x - 16;                   // 64 blocks; 4 per batch
        int b  = gb >> 2;
        if (threadIdx.x == 0) {
            int i0, i1; float v0, v1;
            top2_focus(focus, b, i0, i1, v0, v1);
            sh_i0 = i0; sh_i1 = i1;
        }
        __syncthreads();
        int p4 = (gb & 3)*256 + threadIdx.x;        // float4 index within batch, 0..1023
        int pos = p4 << 2;
        int si = pos >> 8;
        int w  = pos & 255;
        float4 av = make_float4(0.f, 0.f, 0.f, 0.f);
        if (si == sh_i0)      av = *(const float4*)(g_attn + b*GATH + w);
        else if (si == sh_i1) av = *(const float4*)(g_attn + b*GATH + WORDL + w);
        float4 cv = __ldg((const float4*)(coverage + b*SLEN) + p4);
        float4* oa = (float4*)(out + NB*DIM + b*SLEN);
        float4* oc = (float4*)(out + NB*DIM + NB*SLEN + b*SLEN);
        oa[p4] = av;
        oc[p4] = make_float4(cv.x + av.x, cv.y + av.y, cv.z + av.z, cv.w + av.w);
    }
}

extern "C" void kernel_launch(void* const* d_in, const int* in_sizes, int n_in,
                              void* d_out, int out_size) {
    const float* dec_hidden  = (const float*)d_in[0];
    const float* enc_output  = (const float*)d_in[1];
    const float* enc_feature = (const float*)d_in[2];
    const float* enc_mask    = (const float*)d_in[3];
    // d_in[4] = sec_attn (unused by reference)
    const float* coverage    = (const float*)d_in[5];
    const float* focus       = (const float*)d_in[6];
    const float* W_dec       = (const float*)d_in[7];
    const float* b_dec       = (const float*)d_in[8];
    const float* vvec        = (const float*)d_in[9];
    const float* w_cov       = (const float*)d_in[10];
    float* out = (float*)d_out;

    k1_decproj<<<128, 256>>>(dec_hidden, W_dec, b_dec);
    k3_scores<<<1024, 256>>>(enc_feature, coverage, vvec, w_cov, focus);
    k4_softmax<<<16, 512>>>(enc_mask, focus);
    k5_ctx<<<dim3(16, 16), 256>>>(enc_output, focus);
    k6_epilogue<<<80, 256>>>(coverage, focus, out);
}

// round 7
// speedup vs baseline: 1.1152x; 1.0522x over previous
#include <cuda_runtime.h>

#define NB 16
#define SECL 16
#define WORDL 256
#define SLEN 4096
#define DIM 1024
#define FSZ 2
#define GATH (FSZ*WORDL)   // 512
#define NPART 64           // k5 context partials (one per 8-row chunk)

// ---------------- scratch (device globals; no allocation) ----------------
__device__ float g_decfeat[NB*DIM];
__device__ float g_scores[NB*GATH];
__device__ float g_attn[NB*GATH];
__device__ float g_ctxpart[NPART*NB*DIM];   // 4 MB

// accurate tanh: 1 - 2/(e^{2x}+1), ex2/rcp MUFU (~1e-7 abs error)
__device__ __forceinline__ float fast_tanh(float x) {
    float e;
    asm("ex2.approx.f32 %0, %1;" : "=f"(e) : "f"(x * 2.8853900817779268f)); // 2*log2(e)
    float r;
    asm("rcp.approx.f32 %0, %1;" : "=f"(r) : "f"(e + 1.0f));
    return 1.0f - 2.0f * r;
}

// top-2 of focus[b] (jax first-occurrence tie rule); run by ONE thread
__device__ __forceinline__ void top2_focus(const float* __restrict__ focus, int b,
                                           int& i0, int& i1, float& v0, float& v1) {
    const float* f = focus + b*SECL;
    v0 = -__int_as_float(0x7f800000); i0 = 0;
#pragma unroll
    for (int j = 0; j < SECL; j++) { float x = __ldg(&f[j]); if (x > v0) { v0 = x; i0 = j; } }
    v1 = -__int_as_float(0x7f800000); i1 = 0;
#pragma unroll
    for (int j = 0; j < SECL; j++) {
        if (j == i0) continue;
        float x = __ldg(&f[j]); if (x > v1) { v1 = x; i1 = j; }
    }
}

// ---------------- K1: dec_feature = dec_hidden @ W_dec^T + b_dec ----------------
__global__ __launch_bounds__(256) void k1_decproj(const float* __restrict__ h,
                                                  const float* __restrict__ W,
                                                  const float* __restrict__ bvec) {
    int warp = threadIdx.x >> 5;
    int lane = threadIdx.x & 31;
    int d = blockIdx.x*8 + warp;
    const float4* Wd = (const float4*)(W + (size_t)d*DIM);
    const float4* h4 = (const float4*)h;
    float acc[NB];
#pragma unroll
    for (int b = 0; b < NB; b++) acc[b] = 0.f;
#pragma unroll
    for (int i = 0; i < 8; i++) {
        int kk = lane + i*32;
        float4 w = __ldg(&Wd[kk]);
#pragma unroll
        for (int b = 0; b < NB; b++) {
            float4 hb = __ldg(&h4[b*256 + kk]);
            acc[b] = fmaf(w.x, hb.x, fmaf(w.y, hb.y, fmaf(w.z, hb.z, fmaf(w.w, hb.w, acc[b]))));
        }
    }
#pragma unroll
    for (int b = 0; b < NB; b++) {
#pragma unroll
        for (int o = 16; o > 0; o >>= 1)
            acc[b] += __shfl_xor_sync(0xffffffffu, acc[b], o);
    }
    if (lane == 0) {
        float bd = bvec[d];
#pragma unroll
        for (int b = 0; b < NB; b++)
            g_decfeat[b*DIM + d] = acc[b] + bd;
    }
}

// ---------------- K3: scores — enc_feature front-batched (8 independent LDG.128) ----------------
// one warp per gathered position; 1024 blocks * 256 threads (8 warps, same b)
__global__ __launch_bounds__(256) void k3_scores(const float* __restrict__ enc_feature,
                                                 const float* __restrict__ coverage,
                                                 const float* __restrict__ vvec,
                                                 const float* __restrict__ w_cov,
                                                 const float* __restrict__ focus) {
    __shared__ int sh_sec[2];
    int warp = threadIdx.x >> 5;
    int lane = threadIdx.x & 31;
    int gw = blockIdx.x*8 + warp;
    int b = gw >> 9;
    int r = gw & 511;
    if (threadIdx.x == 0) {
        int i0, i1; float v0, v1;
        top2_focus(focus, b, i0, i1, v0, v1);
        sh_sec[0] = i0; sh_sec[1] = i1;
    }
    __syncthreads();
    int sec = sh_sec[r >> 8];
    int s = sec*WORDL + (r & 255);
    float cov = coverage[b*SLEN + s];
    const float4* ef  = (const float4*)(enc_feature + ((size_t)(b*SLEN + s))*DIM) + lane;
    const float4* df  = (const float4*)(g_decfeat + b*DIM) + lane;
    const float4* v4  = (const float4*)vvec + lane;
    const float4* wc4 = (const float4*)w_cov + lane;
    // front-batch the streaming operand: 8 independent LDG.128 in flight
    float4 e0 = __ldg(ef + 0*32);
    float4 e1 = __ldg(ef + 1*32);
    float4 e2 = __ldg(ef + 2*32);
    float4 e3 = __ldg(ef + 3*32);
    float4 e4 = __ldg(ef + 4*32);
    float4 e5 = __ldg(ef + 5*32);
    float4 e6 = __ldg(ef + 6*32);
    float4 e7 = __ldg(ef + 7*32);
    float acc = 0.f;
#define K3_STEP(EV, I) { \
        float4 dd = df[(I)*32]; \
        float4 vv = __ldg(v4 + (I)*32); \
        float4 wc = __ldg(wc4 + (I)*32); \
        acc += vv.x * fast_tanh(fmaf(cov, wc.x, EV.x + dd.x)); \
        acc += vv.y * fast_tanh(fmaf(cov, wc.y, EV.y + dd.y)); \
        acc += vv.z * fast_tanh(fmaf(cov, wc.z, EV.z + dd.z)); \
        acc += vv.w * fast_tanh(fmaf(cov, wc.w, EV.w + dd.w)); }
    K3_STEP(e0, 0) K3_STEP(e1, 1) K3_STEP(e2, 2) K3_STEP(e3, 3)
    K3_STEP(e4, 4) K3_STEP(e5, 5) K3_STEP(e6, 6) K3_STEP(e7, 7)
#undef K3_STEP
#pragma unroll
    for (int o = 16; o > 0; o >>= 1) acc += __shfl_xor_sync(0xffffffffu, acc, o);
    if (lane == 0) g_scores[b*GATH + r] = acc;
}

// ---------------- block reduce helper (512 threads) ----------------
__device__ __forceinline__ float blkred(float v, float* red, bool is_max) {
#pragma unroll
    for (int o = 16; o > 0; o >>= 1) {
        float t = __shfl_xor_sync(0xffffffffu, v, o);
        v = is_max ? fmaxf(v, t) : (v + t);
    }
    __syncthreads();
    if ((threadIdx.x & 31) == 0) red[threadIdx.x >> 5] = v;
    __syncthreads();
    if (threadIdx.x < 32) {
        float x = (threadIdx.x < 16) ? red[threadIdx.x]
                                     : (is_max ? -__int_as_float(0x7f800000) : 0.f);
#pragma unroll
        for (int o = 8; o > 0; o >>= 1) {
            float t = __shfl_xor_sync(0xffffffffu, x, o);
            x = is_max ? fmaxf(x, t) : (x + t);
        }
        if (threadIdx.x == 0) red[0] = x;
    }
    __syncthreads();
    return red[0];
}

// ---------------- K4: softmax (scale-invariant form) -> g_attn ----------------
__global__ __launch_bounds__(512) void k4_softmax(const float* __restrict__ enc_mask,
                                                  const float* __restrict__ focus) {
    __shared__ float red[16];
    __shared__ int   sh_sec[2];
    __shared__ float sh_tv[2];
    int b = blockIdx.x;
    int j = threadIdx.x;
    if (j == 0) {
        int i0, i1; float v0, v1;
        top2_focus(focus, b, i0, i1, v0, v1);
        sh_sec[0] = i0; sh_sec[1] = i1; sh_tv[0] = v0; sh_tv[1] = v1;
    }
    __syncthreads();
    int f = j >> 8;
    int s = sh_sec[f]*WORDL + (j & 255);
    float tv = sh_tv[f];
    float sc = g_scores[b*GATH + j];
    float m  = enc_mask[b*SLEN + s];

    float mx   = blkred(sc, red, true);
    float a0   = __expf(sc - mx) * m;
    float sum2 = blkred(a0, red, false);
    float a1   = tv * (a0 / sum2);
    float sum3 = blkred(a1, red, false);
    g_attn[b*GATH + j] = a1 / sum3;
}

// ---------------- K5: context partials — 8 rows/thread, front-batched (R5-proven) ----------------
// grid (16 b, 64 chunks of 8 rows), 256 threads; thread owns one float4 of DIM.
__global__ __launch_bounds__(256) void k5_ctx(const float* __restrict__ enc_output,
                                              const float* __restrict__ focus) {
    __shared__ float sh_a[8];
    __shared__ int sh_sec;
    int b = blockIdx.x;
    int c = blockIdx.y;            // 0..63
    int f = c >> 5;
    int w0 = (c & 31) * 8;
    if (threadIdx.x == 0) {
        int i0, i1; float v0, v1;
        top2_focus(focus, b, i0, i1, v0, v1);
        sh_sec = f ? i1 : i0;
    }
    if (threadIdx.x >= 32 && threadIdx.x < 40)
        sh_a[threadIdx.x - 32] = g_attn[b*GATH + f*WORDL + w0 + (threadIdx.x - 32)];
    __syncthreads();
    const float4* base = (const float4*)(enc_output
        + ((size_t)(b*SLEN + sh_sec*WORDL + w0))*DIM) + threadIdx.x;
    float4 r0 = __ldg(base + 0*(DIM/4));
    float4 r1 = __ldg(base + 1*(DIM/4));
    float4 r2 = __ldg(base + 2*(DIM/4));
    float4 r3 = __ldg(base + 3*(DIM/4));
    float4 r4 = __ldg(base + 4*(DIM/4));
    float4 r5 = __ldg(base + 5*(DIM/4));
    float4 r6 = __ldg(base + 6*(DIM/4));
    float4 r7 = __ldg(base + 7*(DIM/4));
    float c0 = sh_a[0], c1 = sh_a[1], c2 = sh_a[2], c3 = sh_a[3];
    float c4 = sh_a[4], c5 = sh_a[5], c6 = sh_a[6], c7 = sh_a[7];
    float4 s;
    s.x = (fmaf(c0,r0.x, c1*r1.x) + fmaf(c2,r2.x, c3*r3.x))
        + (fmaf(c4,r4.x, c5*r5.x) + fmaf(c6,r6.x, c7*r7.x));
    s.y = (fmaf(c0,r0.y, c1*r1.y) + fmaf(c2,r2.y, c3*r3.y))
        + (fmaf(c4,r4.y, c5*r5.y) + fmaf(c6,r6.y, c7*r7.y));
    s.z = (fmaf(c0,r0.z, c1*r1.z) + fmaf(c2,r2.z, c3*r3.z))
        + (fmaf(c4,r4.z, c5*r5.z) + fmaf(c6,r6.z, c7*r7.z));
    s.w = (fmaf(c0,r0.w, c1*r1.w) + fmaf(c2,r2.w, c3*r3.w))
        + (fmaf(c4,r4.w, c5*r5.w) + fmaf(c6,r6.w, c7*r7.w));
    *((float4*)(g_ctxpart + ((size_t)(c*NB + b))*DIM) + threadIdx.x) = s;
}

// ---------------- K6: fused epilogue — wide combine + wide scatter ----------------
// blocks [0,64): combine NPART=64 partials, 64 float4 outputs per block.
// blocks [64,128): attn_dist + coverage_out scatter (4 blocks per batch).
__global__ __launch_bounds__(256) void k6_epilogue(const float* __restrict__ coverage,
                                                   const float* __restrict__ focus,
                                                   float* __restrict__ out) {
    if (blockIdx.x < 64) {
        __shared__ float4 sh[4][64];
        int l = threadIdx.x & 63;              // output offset within block
        int g = threadIdx.x >> 6;              // partial group 0..3
        int i = blockIdx.x*64 + l;             // float4 index in [0,4096)
        const float4* cp = (const float4*)g_ctxpart + i;
        float4 s0 = make_float4(0,0,0,0), s1 = s0, s2 = s0, s3 = s0;
#pragma unroll
        for (int p = 0; p < 16; p += 4) {
            float4 t0 = cp[(size_t)(g*16 + p + 0)*(NB*DIM/4)];
            float4 t1 = cp[(size_t)(g*16 + p + 1)*(NB*DIM/4)];
            float4 t2 = cp[(size_t)(g*16 + p + 2)*(NB*DIM/4)];
            float4 t3 = cp[(size_t)(g*16 + p + 3)*(NB*DIM/4)];
            s0.x += t0.x; s0.y += t0.y; s0.z += t0.z; s0.w += t0.w;
            s1.x += t1.x; s1.y += t1.y; s1.z += t1.z; s1.w += t1.w;
            s2.x += t2.x; s2.y += t2.y; s2.z += t2.z; s2.w += t2.w;
            s3.x += t3.x; s3.y += t3.y; s3.z += t3.z; s3.w += t3.w;
        }
        sh[g][l] = make_float4((s0.x+s1.x)+(s2.x+s3.x), (s0.y+s1.y)+(s2.y+s3.y),
                               (s0.z+s1.z)+(s2.z+s3.z), (s0.w+s1.w)+(s2.w+s3.w));
        __syncthreads();
        if (g == 0) {
            float4 a = sh[0][l], b4 = sh[1][l], c4 = sh[2][l], d4 = sh[3][l];
            ((float4*)out)[i] = make_float4((a.x+b4.x)+(c4.x+d4.x), (a.y+b4.y)+(c4.y+d4.y),
                                            (a.z+b4.z)+(c4.z+d4.z), (a.w+b4.w)+(c4.w+d4.w));
        }
    } else {
        __shared__ int sh_i0, sh_i1;
        int gb = blockIdx.x - 64;                   // 64 blocks; 4 per batch
        int b  = gb >> 2;
        if (threadIdx.x == 0) {
            int i0, i1; float v0, v1;
            top2_focus(focus, b, i0, i1, v0, v1);
            sh_i0 = i0; sh_i1 = i1;
        }
        __syncthreads();
        int p4 = (gb & 3)*256 + threadIdx.x;        // float4 index within batch, 0..1023
        int pos = p4 << 2;
        int si = pos >> 8;
        int w  = pos & 255;
        float4 av = make_float4(0.f, 0.f, 0.f, 0.f);
        if (si == sh_i0)      av = *(const float4*)(g_attn + b*GATH + w);
        else if (si == sh_i1) av = *(const float4*)(g_attn + b*GATH + WORDL + w);
        float4 cv = __ldg((const float4*)(coverage + b*SLEN) + p4);
        float4* oa = (float4*)(out + NB*DIM + b*SLEN);
        float4* oc = (float4*)(out + NB*DIM + NB*SLEN + b*SLEN);
        oa[p4] = av;
        oc[p4] = make_float4(cv.x + av.x, cv.y + av.y, cv.z + av.z, cv.w + av.w);
    }
}

extern "C" void kernel_launch(void* const* d_in, const int* in_sizes, int n_in,
                              void* d_out, int out_size) {
    const float* dec_hidden  = (const float*)d_in[0];
    const float* enc_output  = (const float*)d_in[1];
    const float* enc_feature = (const float*)d_in[2];
    const float* enc_mask    = (const float*)d_in[3];
    // d_in[4] = sec_attn (unused by reference)
    const float* coverage    = (const float*)d_in[5];
    const float* focus       = (const float*)d_in[6];
    const float* W_dec       = (const float*)d_in[7];
    const float* b_dec       = (const float*)d_in[8];
    const float* vvec        = (const float*)d_in[9];
    const float* w_cov       = (const float*)d_in[10];
    float* out = (float*)d_out;

    k1_decproj<<<128, 256>>>(dec_hidden, W_dec, b_dec);
    k3_scores<<<1024, 256>>>(enc_feature, coverage, vvec, w_cov, focus);
    k4_softmax<<<16, 512>>>(enc_mask, focus);
    k5_ctx<<<dim3(16, 64), 256>>>(enc_output, focus);
    k6_epilogue<<<128, 256>>>(coverage, focus, out);
}